// round 4
// baseline (speedup 1.0000x reference)
#include <cuda_runtime.h>
#include <cuda_fp16.h>

#define N_POINTS 1000000
#define GRID_D   128
#define CH       32
#define NVOX     (GRID_D * GRID_D * GRID_D)   // 2,097,152
#define NBUCKET  4096                         // 16x16x16 coarse cells

// Feature transposed to (D,H,W,C) in half: one voxel's 32 channels = 64B.
__device__ __half g_feat_h[(size_t)NVOX * CH];
// Counting-sort scratch
__device__ int g_hist[NBUCKET];
__device__ int g_off[NBUCKET];
__device__ int g_perm[N_POINTS];

// ---------------------------------------------------------------------------
// coarse spatial key: 16^3 cells of 8^3 voxels each
// ---------------------------------------------------------------------------
__device__ __forceinline__ int point_key(const float* __restrict__ x, int p) {
    const float fx = fmaf(__ldg(&x[3 * p + 0]), 6.4f, 63.5f);
    const float fy = fmaf(__ldg(&x[3 * p + 1]), 6.4f, 63.5f);
    const float fz = fmaf(__ldg(&x[3 * p + 2]), 6.4f, 63.5f);
    const int cx = min(max((int)floorf(fx), 0), GRID_D - 1);
    const int cy = min(max((int)floorf(fy), 0), GRID_D - 1);
    const int cz = min(max((int)floorf(fz), 0), GRID_D - 1);
    return (((cz >> 3) * 16) + (cy >> 3)) * 16 + (cx >> 3);
}

__global__ void zero_hist() {
    const int i = blockIdx.x * blockDim.x + threadIdx.x;
    if (i < NBUCKET) g_hist[i] = 0;
}

__global__ __launch_bounds__(1024) void hist_kernel(const float* __restrict__ x) {
    __shared__ int sh[NBUCKET];
    for (int i = threadIdx.x; i < NBUCKET; i += blockDim.x) sh[i] = 0;
    __syncthreads();
    for (int p = blockIdx.x * blockDim.x + threadIdx.x; p < N_POINTS;
         p += gridDim.x * blockDim.x)
        atomicAdd(&sh[point_key(x, p)], 1);
    __syncthreads();
    for (int i = threadIdx.x; i < NBUCKET; i += blockDim.x)
        if (sh[i]) atomicAdd(&g_hist[i], sh[i]);
}

// exclusive scan of 4096 counters, one block of 1024 threads (4 each)
__global__ __launch_bounds__(1024) void scan_kernel() {
    __shared__ int warp_sums[32];
    const int t = threadIdx.x, lane = t & 31, wid = t >> 5;
    int v[4], s = 0;
    #pragma unroll
    for (int k = 0; k < 4; ++k) { v[k] = g_hist[t * 4 + k]; s += v[k]; }
    int ss = s;                               // inclusive scan within warp
    #pragma unroll
    for (int o = 1; o < 32; o <<= 1) {
        int n = __shfl_up_sync(0xffffffff, ss, o);
        if (lane >= o) ss += n;
    }
    if (lane == 31) warp_sums[wid] = ss;
    __syncthreads();
    if (wid == 0) {
        int ws = warp_sums[lane];
        #pragma unroll
        for (int o = 1; o < 32; o <<= 1) {
            int n = __shfl_up_sync(0xffffffff, ws, o);
            if (lane >= o) ws += n;
        }
        warp_sums[lane] = ws;
    }
    __syncthreads();
    int run = (wid > 0 ? warp_sums[wid - 1] : 0) + (ss - s);  // exclusive base
    #pragma unroll
    for (int k = 0; k < 4; ++k) { g_off[t * 4 + k] = run; run += v[k]; }
}

__global__ __launch_bounds__(1024) void scatter_kernel(const float* __restrict__ x) {
    const int p = blockIdx.x * blockDim.x + threadIdx.x;
    if (p >= N_POINTS) return;
    const int pos = atomicAdd(&g_off[point_key(x, p)], 1);
    g_perm[pos] = p;
}

// ---------------------------------------------------------------------------
// Kernel 1: transpose (C, V) fp32 -> (V, C) fp16. (unchanged, ~5.6 TB/s)
// ---------------------------------------------------------------------------
__global__ __launch_bounds__(256) void transpose_feat(const float* __restrict__ feature) {
    __shared__ float tile[32 * 256];
    const int t  = threadIdx.x;
    const int s0 = blockIdx.x * 256;

    float4 v[8];
    #pragma unroll
    for (int r = 0; r < 8; ++r) {
        const int i  = r * 256 + t;
        const int ch = i >> 6;
        const int c4 = i & 63;
        v[r] = __ldg(reinterpret_cast<const float4*>(
                  &feature[(size_t)ch * NVOX + s0 + c4 * 4]));
    }
    #pragma unroll
    for (int r = 0; r < 8; ++r) {
        const int i   = r * 256 + t;
        const int ch  = i >> 6;
        const int c4  = i & 63;
        const int col = (c4 * 4) ^ ((ch >> 2) * 4);
        *reinterpret_cast<float4*>(&tile[ch * 256 + col]) = v[r];
    }
    __syncthreads();

    #pragma unroll
    for (int r = 0; r < 4; ++r) {
        const int i   = r * 256 + t;
        const int vox = i >> 2;
        const int oct = i & 3;
        half2 h[4];
        #pragma unroll
        for (int kk = 0; kk < 4; ++kk) {
            const int ch0 = oct * 8 + kk * 2;
            const int ch1 = ch0 + 1;
            const float a = tile[ch0 * 256 + (vox ^ ((ch0 >> 2) * 4))];
            const float b = tile[ch1 * 256 + (vox ^ ((ch1 >> 2) * 4))];
            h[kk] = __floats2half2_rn(a, b);
        }
        uint4 o;
        o.x = *reinterpret_cast<unsigned*>(&h[0]);
        o.y = *reinterpret_cast<unsigned*>(&h[1]);
        o.z = *reinterpret_cast<unsigned*>(&h[2]);
        o.w = *reinterpret_cast<unsigned*>(&h[3]);
        *reinterpret_cast<uint4*>(&g_feat_h[(size_t)(s0 + vox) * CH + oct * 8]) = o;
    }
}

// ---------------------------------------------------------------------------
// Kernel 2: trilinear gather over bucket-sorted points. 4 lanes per point,
// each lane owns 8 channels (16B/corner). 8 corner loads batched -> MLP=8.
// ---------------------------------------------------------------------------
__global__ __launch_bounds__(256) void gather_trilinear(const float* __restrict__ x,
                                                        float* __restrict__ out) {
    const int tid = blockIdx.x * blockDim.x + threadIdx.x;
    const int i   = tid >> 2;                 // sorted slot
    const int q   = tid & 3;                  // channel octet
    if (i >= N_POINTS) return;
    const int p = g_perm[i];                  // 4 lanes share -> L1 broadcast

    const float px = __ldg(&x[3 * p + 0]);
    const float py = __ldg(&x[3 * p + 1]);
    const float pz = __ldg(&x[3 * p + 2]);

    const float fx = fmaf(px, 6.4f, 63.5f);
    const float fy = fmaf(py, 6.4f, 63.5f);
    const float fz = fmaf(pz, 6.4f, 63.5f);

    const float x0f = floorf(fx), y0f = floorf(fy), z0f = floorf(fz);
    const float wx = fx - x0f, wy = fy - y0f, wz = fz - z0f;
    const int x0 = (int)x0f, y0 = (int)y0f, z0 = (int)z0f;

    float  w[8];
    size_t idx[8];
    #pragma unroll
    for (int c = 0; c < 8; ++c) {
        const int dx = c & 1, dy = (c >> 1) & 1, dz = (c >> 2) & 1;
        const int xi = x0 + dx, yi = y0 + dy, zi = z0 + dz;
        const bool vld = (xi >= 0) && (xi < GRID_D) &&
                         (yi >= 0) && (yi < GRID_D) &&
                         (zi >= 0) && (zi < GRID_D);
        const int cx = min(max(xi, 0), GRID_D - 1);
        const int cy = min(max(yi, 0), GRID_D - 1);
        const int cz = min(max(zi, 0), GRID_D - 1);
        const float wxt = dx ? wx : 1.0f - wx;
        const float wyt = dy ? wy : 1.0f - wy;
        const float wzt = dz ? wz : 1.0f - wz;
        w[c]   = vld ? (wxt * wyt * wzt) : 0.0f;
        idx[c] = ((size_t)((cz * GRID_D + cy) * GRID_D + cx)) * CH + q * 8;
    }

    uint4 cv[8];
    #pragma unroll
    for (int c = 0; c < 8; ++c)
        cv[c] = *reinterpret_cast<const uint4*>(&g_feat_h[idx[c]]);

    float acc[8] = {0.f, 0.f, 0.f, 0.f, 0.f, 0.f, 0.f, 0.f};
    #pragma unroll
    for (int c = 0; c < 8; ++c) {
        const unsigned u[4] = {cv[c].x, cv[c].y, cv[c].z, cv[c].w};
        #pragma unroll
        for (int kk = 0; kk < 4; ++kk) {
            const half2  h2 = *reinterpret_cast<const half2*>(&u[kk]);
            const float2 f2 = __half22float2(h2);
            acc[kk * 2 + 0] = fmaf(w[c], f2.x, acc[kk * 2 + 0]);
            acc[kk * 2 + 1] = fmaf(w[c], f2.y, acc[kk * 2 + 1]);
        }
    }

    float* op = out + (size_t)p * CH + q * 8;
    *reinterpret_cast<float4*>(op)     = make_float4(acc[0], acc[1], acc[2], acc[3]);
    *reinterpret_cast<float4*>(op + 4) = make_float4(acc[4], acc[5], acc[6], acc[7]);
}

extern "C" void kernel_launch(void* const* d_in, const int* in_sizes, int n_in,
                              void* d_out, int out_size) {
    const float* x       = (const float*)d_in[0];   // (N_POINTS, 3)
    const float* feature = (const float*)d_in[1];   // (32, 128, 128, 128)
    float*       out     = (float*)d_out;           // (N_POINTS, 32)

    // counting sort by coarse spatial cell
    zero_hist<<<(NBUCKET + 255) / 256, 256>>>();
    hist_kernel<<<148, 1024>>>(x);
    scan_kernel<<<1, 1024>>>();
    scatter_kernel<<<(N_POINTS + 1023) / 1024, 1024>>>(x);

    // grid transpose (fp32 channel-major -> fp16 voxel-major)
    transpose_feat<<<NVOX / 256, 256>>>(feature);

    // gather in bucket order
    const int total = N_POINTS * 4;
    gather_trilinear<<<(total + 255) / 256, 256>>>(x, out);
}